// round 1
// baseline (speedup 1.0000x reference)
#include <cuda_runtime.h>
#include <cuda_bf16.h>
#include <cstddef>

// ---------------------------------------------------------------------------
// Problem constants (fixed shapes from the reference)
// ---------------------------------------------------------------------------
#define N_NODES 100000
#define N_EDGES 3200000
#define IN_FEAT 512
#define HIDDEN  256
#define CLASSES 64

// ---------------------------------------------------------------------------
// Scratch (no cudaMalloc allowed) — __device__ globals
// ---------------------------------------------------------------------------
__device__ float g_sup1[(size_t)N_NODES * HIDDEN];   // X @ W1          (102.4 MB)
__device__ float g_agg1[(size_t)N_NODES * HIDDEN];   // A @ sup1        (102.4 MB)
__device__ float g_sup2[(size_t)N_NODES * CLASSES];  // relu(..) @ W2   ( 25.6 MB)

// ---------------------------------------------------------------------------
// Zero kernel (float4)
// ---------------------------------------------------------------------------
__global__ void zero_kernel(float4* __restrict__ p, int n4) {
    int i = blockIdx.x * blockDim.x + threadIdx.x;
    if (i < n4) p[i] = make_float4(0.f, 0.f, 0.f, 0.f);
}

// ---------------------------------------------------------------------------
// Tiled fp32 GEMM: C[M,N] = op(A)[M,K] @ B[K,N]
//   FUSE: op(A) = relu(A + bias[k])  (bias indexed by K-dim = feature index)
//   blockDim = (BM/TM)*(BN/TN) must be 256.
// ---------------------------------------------------------------------------
template <int BM, int BN, int BK, int TM, int TN, bool FUSE>
__global__ __launch_bounds__(256)
void sgemm_kernel(const float* __restrict__ A, const float* __restrict__ B,
                  const float* __restrict__ bias, float* __restrict__ C,
                  int M, int N, int K) {
    __shared__ float As[BK][BM];   // transposed A tile
    __shared__ float Bs[BK][BN];

    const int tid  = threadIdx.x;
    const int brow = blockIdx.y;
    const int bcol = blockIdx.x;

    const int tcol = tid % (BN / TN);
    const int trow = tid / (BN / TN);

    float acc[TM][TN];
#pragma unroll
    for (int i = 0; i < TM; i++)
#pragma unroll
        for (int j = 0; j < TN; j++) acc[i][j] = 0.f;

    for (int k0 = 0; k0 < K; k0 += BK) {
        // ---- load A tile (BM x BK), store transposed ----
#pragma unroll
        for (int idx = tid; idx < BM * BK / 4; idx += 256) {
            int r  = idx / (BK / 4);
            int c4 = idx % (BK / 4);
            int grow = brow * BM + r;
            float4 v = make_float4(0.f, 0.f, 0.f, 0.f);
            if (grow < M)
                v = *reinterpret_cast<const float4*>(A + (size_t)grow * K + k0 + c4 * 4);
            if (FUSE) {
                float4 bb = *reinterpret_cast<const float4*>(bias + k0 + c4 * 4);
                v.x = fmaxf(v.x + bb.x, 0.f);
                v.y = fmaxf(v.y + bb.y, 0.f);
                v.z = fmaxf(v.z + bb.z, 0.f);
                v.w = fmaxf(v.w + bb.w, 0.f);
            }
            As[c4 * 4 + 0][r] = v.x;
            As[c4 * 4 + 1][r] = v.y;
            As[c4 * 4 + 2][r] = v.z;
            As[c4 * 4 + 3][r] = v.w;
        }
        // ---- load B tile (BK x BN) ----
#pragma unroll
        for (int idx = tid; idx < BK * BN / 4; idx += 256) {
            int r  = idx / (BN / 4);
            int c4 = idx % (BN / 4);
            float4 v = *reinterpret_cast<const float4*>(B + (size_t)(k0 + r) * N + bcol * BN + c4 * 4);
            *reinterpret_cast<float4*>(&Bs[r][c4 * 4]) = v;
        }
        __syncthreads();

        // ---- compute ----
#pragma unroll
        for (int k = 0; k < BK; k++) {
            float a[TM], b[TN];
#pragma unroll
            for (int i = 0; i < TM; i += 4) {
                float4 v = *reinterpret_cast<const float4*>(&As[k][trow * TM + i]);
                a[i + 0] = v.x; a[i + 1] = v.y; a[i + 2] = v.z; a[i + 3] = v.w;
            }
#pragma unroll
            for (int j = 0; j < TN; j += 4) {
                float4 v = *reinterpret_cast<const float4*>(&Bs[k][tcol * TN + j]);
                b[j + 0] = v.x; b[j + 1] = v.y; b[j + 2] = v.z; b[j + 3] = v.w;
            }
#pragma unroll
            for (int i = 0; i < TM; i++)
#pragma unroll
                for (int j = 0; j < TN; j++) acc[i][j] += a[i] * b[j];
        }
        __syncthreads();
    }

    // ---- store C ----
#pragma unroll
    for (int i = 0; i < TM; i++) {
        int grow = brow * BM + trow * TM + i;
        if (grow < M) {
#pragma unroll
            for (int j = 0; j < TN; j += 4) {
                float4 v = make_float4(acc[i][j], acc[i][j + 1], acc[i][j + 2], acc[i][j + 3]);
                *reinterpret_cast<float4*>(C + (size_t)grow * N + bcol * BN + tcol * TN + j) = v;
            }
        }
    }
}

// ---------------------------------------------------------------------------
// SpMM scatter: agg[dst[e]] += w[e] * sup[src[e]]   (F = features, 256 or 64)
// One thread per (edge, float4-of-features). F/4 threads per edge.
// ---------------------------------------------------------------------------
template <int F>
__global__ __launch_bounds__(256)
void spmm_kernel(const float* __restrict__ sup,
                 const int* __restrict__ esrc, const int* __restrict__ edst,
                 const float* __restrict__ ew, float* __restrict__ agg,
                 int n_edges) {
    constexpr int Q = F / 4;  // float4s per edge (power of 2)
    long long tid = (long long)blockIdx.x * blockDim.x + threadIdx.x;
    long long total = (long long)n_edges * Q;
    if (tid >= total) return;
    int e = (int)(tid / Q);
    int q = (int)(tid % Q);

    int   s = __ldg(esrc + e);
    int   d = __ldg(edst + e);
    float w = __ldg(ew + e);

    float4 v = __ldg(reinterpret_cast<const float4*>(sup + (size_t)s * F) + q);
    v.x *= w; v.y *= w; v.z *= w; v.w *= w;

    float* p = agg + (size_t)d * F + q * 4;
    asm volatile("red.global.add.v4.f32 [%0], {%1, %2, %3, %4};"
                 :: "l"(p), "f"(v.x), "f"(v.y), "f"(v.z), "f"(v.w)
                 : "memory");
}

// ---------------------------------------------------------------------------
// In-place log_softmax over 64 classes, + bias b2. One warp per row.
// ---------------------------------------------------------------------------
__global__ __launch_bounds__(256)
void logsoftmax_kernel(float* __restrict__ out, const float* __restrict__ b2, int M) {
    int row  = blockIdx.x * (blockDim.x / 32) + (threadIdx.x >> 5);
    int lane = threadIdx.x & 31;
    if (row >= M) return;
    float* p = out + (size_t)row * CLASSES;

    float v0 = p[lane]      + __ldg(b2 + lane);
    float v1 = p[lane + 32] + __ldg(b2 + lane + 32);

    float m = fmaxf(v0, v1);
#pragma unroll
    for (int o = 16; o; o >>= 1) m = fmaxf(m, __shfl_xor_sync(0xFFFFFFFFu, m, o));

    float s = expf(v0 - m) + expf(v1 - m);
#pragma unroll
    for (int o = 16; o; o >>= 1) s += __shfl_xor_sync(0xFFFFFFFFu, s, o);

    float lse = m + logf(s);
    p[lane]      = v0 - lse;
    p[lane + 32] = v1 - lse;
}

// ---------------------------------------------------------------------------
// kernel_launch
// ---------------------------------------------------------------------------
extern "C" void kernel_launch(void* const* d_in, const int* in_sizes, int n_in,
                              void* d_out, int out_size) {
    const float* x    = (const float*)d_in[0];
    const float* w1   = (const float*)d_in[1];
    const float* b1   = (const float*)d_in[2];
    const float* w2   = (const float*)d_in[3];
    const float* b2   = (const float*)d_in[4];
    const float* ew   = (const float*)d_in[5];
    const int*   esrc = (const int*)d_in[6];
    const int*   edst = (const int*)d_in[7];
    float*       out  = (float*)d_out;

    float *sup1, *agg1, *sup2;
    cudaGetSymbolAddress((void**)&sup1, g_sup1);
    cudaGetSymbolAddress((void**)&agg1, g_agg1);
    cudaGetSymbolAddress((void**)&sup2, g_sup2);

    // 1) zero agg1 and d_out (atomic accumulation targets)
    {
        int n4 = N_NODES * HIDDEN / 4;       // 6.4M
        zero_kernel<<<(n4 + 255) / 256, 256>>>((float4*)agg1, n4);
    }
    {
        int n4 = N_NODES * CLASSES / 4;      // 1.6M
        zero_kernel<<<(n4 + 255) / 256, 256>>>((float4*)out, n4);
    }

    // 2) sup1 = X @ W1    [100000,512] @ [512,256]
    {
        dim3 grid(HIDDEN / 128, (N_NODES + 127) / 128);
        sgemm_kernel<128, 128, 8, 8, 8, false><<<grid, 256>>>(
            x, w1, nullptr, sup1, N_NODES, HIDDEN, IN_FEAT);
    }

    // 3) agg1[dst] += w * sup1[src]  (F=256)
    {
        long long total = (long long)N_EDGES * (HIDDEN / 4);   // 204.8M
        int blocks = (int)((total + 255) / 256);
        spmm_kernel<HIDDEN><<<blocks, 256>>>(sup1, esrc, edst, ew, agg1, N_EDGES);
    }

    // 4) sup2 = relu(agg1 + b1) @ W2   [100000,256] @ [256,64]  (fused bias+relu)
    {
        dim3 grid(CLASSES / 64, (N_NODES + 127) / 128);
        sgemm_kernel<128, 64, 8, 8, 4, true><<<grid, 256>>>(
            agg1, w2, b1, sup2, N_NODES, CLASSES, HIDDEN);
    }

    // 5) out[dst] += w * sup2[src]  (F=64)
    {
        long long total = (long long)N_EDGES * (CLASSES / 4);  // 51.2M
        int blocks = (int)((total + 255) / 256);
        spmm_kernel<CLASSES><<<blocks, 256>>>(sup2, esrc, edst, ew, out, N_EDGES);
    }

    // 6) out = log_softmax(out + b2)  in place
    {
        int rows_per_block = 256 / 32;
        int blocks = (N_NODES + rows_per_block - 1) / rows_per_block;
        logsoftmax_kernel<<<blocks, 256>>>(out, b2, N_NODES);
    }
}

// round 4
// speedup vs baseline: 1.7221x; 1.7221x over previous
#include <cuda_runtime.h>
#include <cuda_bf16.h>
#include <cstddef>
#include <cstdint>

// ---------------------------------------------------------------------------
// Problem constants
// ---------------------------------------------------------------------------
#define N_NODES 100000
#define N_EDGES 3200000
#define IN_FEAT 512
#define HIDDEN  256
#define CLASSES 64

// ---------------------------------------------------------------------------
// Scratch (__device__ globals; no cudaMalloc allowed)
// ---------------------------------------------------------------------------
__device__ float g_sup1[(size_t)N_NODES * HIDDEN];   // X @ W1
__device__ float g_agg1[(size_t)N_NODES * HIDDEN];   // A @ sup1
__device__ float g_sup2[(size_t)N_NODES * CLASSES];  // relu(..) @ W2
__device__ int   g_deg[N_NODES];
__device__ int   g_rowptr[N_NODES + 1];
__device__ int   g_cursor[N_NODES];
__device__ int   g_col[N_EDGES];
__device__ float g_wv[N_EDGES];

// ---------------------------------------------------------------------------
// Zero kernel for the degree histogram
// ---------------------------------------------------------------------------
__global__ void zero_int_kernel(int* __restrict__ p, int n) {
    int i = blockIdx.x * blockDim.x + threadIdx.x;
    if (i < n) p[i] = 0;
}

// ---------------------------------------------------------------------------
// CSR build: histogram -> scan -> fill
// ---------------------------------------------------------------------------
__global__ void hist_kernel(const int* __restrict__ edst, int* __restrict__ deg) {
    int i = blockIdx.x * blockDim.x + threadIdx.x;
    if (i < N_EDGES) atomicAdd(&deg[__ldg(edst + i)], 1);
}

// Single-block exclusive scan over N_NODES degrees -> rowptr, cursor
__global__ __launch_bounds__(1024)
void scan_kernel(const int* __restrict__ deg, int* __restrict__ rowptr,
                 int* __restrict__ cursor) {
    __shared__ int sums[1024];
    const int CH = (N_NODES + 1023) / 1024;  // 98
    int t = threadIdx.x;
    int base = t * CH;
    int s = 0;
    for (int i = 0; i < CH; i++) {
        int idx = base + i;
        if (idx < N_NODES) s += deg[idx];
    }
    sums[t] = s;
    __syncthreads();
    // inclusive Hillis-Steele scan
    for (int off = 1; off < 1024; off <<= 1) {
        int v = (t >= off) ? sums[t - off] : 0;
        __syncthreads();
        sums[t] += v;
        __syncthreads();
    }
    int run = (t == 0) ? 0 : sums[t - 1];
    for (int i = 0; i < CH; i++) {
        int idx = base + i;
        if (idx < N_NODES) {
            rowptr[idx] = run;
            cursor[idx] = run;
            run += deg[idx];
        }
    }
    if (t == 1023) rowptr[N_NODES] = run;  // tail chunks are empty -> run == total
}

__global__ void fill_kernel(const int* __restrict__ esrc, const int* __restrict__ edst,
                            const float* __restrict__ ew,
                            int* __restrict__ cursor, int* __restrict__ col,
                            float* __restrict__ wv) {
    int e = blockIdx.x * blockDim.x + threadIdx.x;
    if (e < N_EDGES) {
        int d = __ldg(edst + e);
        int pos = atomicAdd(&cursor[d], 1);
        col[pos] = __ldg(esrc + e);
        wv[pos] = __ldg(ew + e);
    }
}

// ---------------------------------------------------------------------------
// GEMM1: C[M,256] = A[M,512] @ B[512,256] via tf32 mma.sync (fp32 accum)
// BM=128 BN=128 BK=32, 8 warps (2x4), warp tile 64x32, m16n8k8.
// ---------------------------------------------------------------------------
__device__ __forceinline__ void cp_async16(void* sdst, const void* gsrc) {
    uint32_t sa = (uint32_t)__cvta_generic_to_shared(sdst);
    asm volatile("cp.async.cg.shared.global [%0], [%1], 16;" :: "r"(sa), "l"(gsrc));
}

__global__ __launch_bounds__(256, 2)
void gemm_tf32_kernel(const float* __restrict__ A, const float* __restrict__ B,
                      float* __restrict__ C, int M) {
    constexpr int K = IN_FEAT;   // 512
    constexpr int N = HIDDEN;    // 256
    __shared__ float As[128 * 36];  // [row][k] stride 36 (pad for conflict-free frags)
    __shared__ float Bs[32 * 136];  // [k][n] stride 136

    const int tid = threadIdx.x;
    const int brow = blockIdx.y, bcol = blockIdx.x;
    const int warp = tid >> 5, lane = tid & 31;
    const int wm = warp & 1, wn = warp >> 1;   // 2 x 4 warp grid
    const int g = lane >> 2, t = lane & 3;

    float c[4][4][4];
#pragma unroll
    for (int i = 0; i < 4; i++)
#pragma unroll
        for (int j = 0; j < 4; j++) {
            c[i][j][0] = 0.f; c[i][j][1] = 0.f; c[i][j][2] = 0.f; c[i][j][3] = 0.f;
        }

#pragma unroll 1
    for (int k0 = 0; k0 < K; k0 += 32) {
        // ---- A tile: 128x32 = 1024 float4, 4 per thread ----
#pragma unroll
        for (int u = 0; u < 4; u++) {
            int f = tid + u * 256;
            int r = f >> 3, c4 = f & 7;
            int grow = brow * 128 + r;
            float* sdst = &As[r * 36 + c4 * 4];
            if (grow < M)
                cp_async16(sdst, A + (size_t)grow * K + k0 + c4 * 4);
            else
                *reinterpret_cast<float4*>(sdst) = make_float4(0.f, 0.f, 0.f, 0.f);
        }
        // ---- B tile: 32x128 = 1024 float4 ----
#pragma unroll
        for (int u = 0; u < 4; u++) {
            int f = tid + u * 256;
            int r = f >> 5, c4 = f & 31;
            cp_async16(&Bs[r * 136 + c4 * 4],
                       B + (size_t)(k0 + r) * N + bcol * 128 + c4 * 4);
        }
        asm volatile("cp.async.commit_group;");
        asm volatile("cp.async.wait_group 0;");
        __syncthreads();

#pragma unroll
        for (int ks = 0; ks < 4; ks++) {
            const int k = ks * 8;
            uint32_t a[4][4], b[4][2];
#pragma unroll
            for (int i = 0; i < 4; i++) {
                int m = wm * 64 + i * 16;
                a[i][0] = __float_as_uint(As[(m + g) * 36 + k + t]);
                a[i][1] = __float_as_uint(As[(m + g + 8) * 36 + k + t]);
                a[i][2] = __float_as_uint(As[(m + g) * 36 + k + t + 4]);
                a[i][3] = __float_as_uint(As[(m + g + 8) * 36 + k + t + 4]);
            }
#pragma unroll
            for (int j = 0; j < 4; j++) {
                int n = wn * 32 + j * 8;
                b[j][0] = __float_as_uint(Bs[(k + t) * 136 + n + g]);
                b[j][1] = __float_as_uint(Bs[(k + t + 4) * 136 + n + g]);
            }
#pragma unroll
            for (int i = 0; i < 4; i++)
#pragma unroll
                for (int j = 0; j < 4; j++) {
                    asm volatile(
                        "mma.sync.aligned.m16n8k8.row.col.f32.tf32.tf32.f32 "
                        "{%0,%1,%2,%3},{%4,%5,%6,%7},{%8,%9},{%0,%1,%2,%3};"
                        : "+f"(c[i][j][0]), "+f"(c[i][j][1]),
                          "+f"(c[i][j][2]), "+f"(c[i][j][3])
                        : "r"(a[i][0]), "r"(a[i][1]), "r"(a[i][2]), "r"(a[i][3]),
                          "r"(b[j][0]), "r"(b[j][1]));
                }
        }
        __syncthreads();
    }

    // ---- epilogue ----
#pragma unroll
    for (int i = 0; i < 4; i++) {
        int r0 = brow * 128 + wm * 64 + i * 16 + g;
#pragma unroll
        for (int j = 0; j < 4; j++) {
            int cc = bcol * 128 + wn * 32 + j * 8 + 2 * t;
            if (r0 < M)
                *reinterpret_cast<float2*>(C + (size_t)r0 * N + cc) =
                    make_float2(c[i][j][0], c[i][j][1]);
            if (r0 + 8 < M)
                *reinterpret_cast<float2*>(C + (size_t)(r0 + 8) * N + cc) =
                    make_float2(c[i][j][2], c[i][j][3]);
        }
    }
}

// ---------------------------------------------------------------------------
// SIMT GEMM (GEMM2): C = relu(A + bias) @ B, fused bias+ReLU on A
// ---------------------------------------------------------------------------
template <int BM, int BN, int BK, int TM, int TN>
__global__ __launch_bounds__(256)
void sgemm_fused_kernel(const float* __restrict__ A, const float* __restrict__ B,
                        const float* __restrict__ bias, float* __restrict__ C,
                        int M, int N, int K) {
    __shared__ float As[BK][BM];
    __shared__ float Bs[BK][BN];

    const int tid = threadIdx.x;
    const int brow = blockIdx.y;
    const int bcol = blockIdx.x;
    const int tcol = tid % (BN / TN);
    const int trow = tid / (BN / TN);

    float acc[TM][TN];
#pragma unroll
    for (int i = 0; i < TM; i++)
#pragma unroll
        for (int j = 0; j < TN; j++) acc[i][j] = 0.f;

#pragma unroll 1
    for (int k0 = 0; k0 < K; k0 += BK) {
#pragma unroll
        for (int idx = tid; idx < BM * BK / 4; idx += 256) {
            int r = idx / (BK / 4);
            int c4 = idx % (BK / 4);
            int grow = brow * BM + r;
            float4 v = make_float4(0.f, 0.f, 0.f, 0.f);
            if (grow < M)
                v = *reinterpret_cast<const float4*>(A + (size_t)grow * K + k0 + c4 * 4);
            float4 bb = *reinterpret_cast<const float4*>(bias + k0 + c4 * 4);
            v.x = fmaxf(v.x + bb.x, 0.f);
            v.y = fmaxf(v.y + bb.y, 0.f);
            v.z = fmaxf(v.z + bb.z, 0.f);
            v.w = fmaxf(v.w + bb.w, 0.f);
            As[c4 * 4 + 0][r] = v.x;
            As[c4 * 4 + 1][r] = v.y;
            As[c4 * 4 + 2][r] = v.z;
            As[c4 * 4 + 3][r] = v.w;
        }
#pragma unroll
        for (int idx = tid; idx < BK * BN / 4; idx += 256) {
            int r = idx / (BN / 4);
            int c4 = idx % (BN / 4);
            float4 v = *reinterpret_cast<const float4*>(
                B + (size_t)(k0 + r) * N + bcol * BN + c4 * 4);
            *reinterpret_cast<float4*>(&Bs[r][c4 * 4]) = v;
        }
        __syncthreads();

#pragma unroll
        for (int k = 0; k < BK; k++) {
            float a[TM], b[TN];
#pragma unroll
            for (int i = 0; i < TM; i += 4) {
                float4 v = *reinterpret_cast<const float4*>(&As[k][trow * TM + i]);
                a[i + 0] = v.x; a[i + 1] = v.y; a[i + 2] = v.z; a[i + 3] = v.w;
            }
#pragma unroll
            for (int j = 0; j < TN; j += 4) {
                float4 v = *reinterpret_cast<const float4*>(&Bs[k][tcol * TN + j]);
                b[j + 0] = v.x; b[j + 1] = v.y; b[j + 2] = v.z; b[j + 3] = v.w;
            }
#pragma unroll
            for (int i = 0; i < TM; i++)
#pragma unroll
                for (int j = 0; j < TN; j++) acc[i][j] += a[i] * b[j];
        }
        __syncthreads();
    }

#pragma unroll
    for (int i = 0; i < TM; i++) {
        int grow = brow * BM + trow * TM + i;
        if (grow < M) {
#pragma unroll
            for (int j = 0; j < TN; j += 4) {
                float4 v = make_float4(acc[i][j], acc[i][j + 1], acc[i][j + 2], acc[i][j + 3]);
                *reinterpret_cast<float4*>(C + (size_t)grow * N + bcol * BN + tcol * TN + j) = v;
            }
        }
    }
}

// ---------------------------------------------------------------------------
// Gather SpMM, F=256: one block (256 thr) per dst row. No atomics.
// ---------------------------------------------------------------------------
__global__ __launch_bounds__(256)
void spmm_gather256(const float* __restrict__ sup, const int* __restrict__ rowptr,
                    const int* __restrict__ col, const float* __restrict__ wv,
                    float* __restrict__ out) {
    int row = blockIdx.x;
    int f = threadIdx.x;
    int beg = __ldg(rowptr + row), end = __ldg(rowptr + row + 1);
    float acc0 = 0.f, acc1 = 0.f, acc2 = 0.f, acc3 = 0.f;
    int e = beg;
    for (; e + 4 <= end; e += 4) {
        int s0 = __ldg(col + e),     s1 = __ldg(col + e + 1);
        int s2 = __ldg(col + e + 2), s3 = __ldg(col + e + 3);
        float w0 = __ldg(wv + e),     w1 = __ldg(wv + e + 1);
        float w2 = __ldg(wv + e + 2), w3 = __ldg(wv + e + 3);
        acc0 += w0 * __ldg(sup + (size_t)s0 * HIDDEN + f);
        acc1 += w1 * __ldg(sup + (size_t)s1 * HIDDEN + f);
        acc2 += w2 * __ldg(sup + (size_t)s2 * HIDDEN + f);
        acc3 += w3 * __ldg(sup + (size_t)s3 * HIDDEN + f);
    }
    for (; e < end; e++)
        acc0 += __ldg(wv + e) * __ldg(sup + (size_t)__ldg(col + e) * HIDDEN + f);
    out[(size_t)row * HIDDEN + f] = acc0 + acc1 + acc2 + acc3;
}

// Gather SpMM, F=64: 4 rows per 256-thread block.
__global__ __launch_bounds__(256)
void spmm_gather64(const float* __restrict__ sup, const int* __restrict__ rowptr,
                   const int* __restrict__ col, const float* __restrict__ wv,
                   float* __restrict__ out) {
    int row = blockIdx.x * 4 + (threadIdx.x >> 6);
    int f = threadIdx.x & 63;
    if (row >= N_NODES) return;
    int beg = __ldg(rowptr + row), end = __ldg(rowptr + row + 1);
    float acc0 = 0.f, acc1 = 0.f, acc2 = 0.f, acc3 = 0.f;
    int e = beg;
    for (; e + 4 <= end; e += 4) {
        int s0 = __ldg(col + e),     s1 = __ldg(col + e + 1);
        int s2 = __ldg(col + e + 2), s3 = __ldg(col + e + 3);
        float w0 = __ldg(wv + e),     w1 = __ldg(wv + e + 1);
        float w2 = __ldg(wv + e + 2), w3 = __ldg(wv + e + 3);
        acc0 += w0 * __ldg(sup + (size_t)s0 * CLASSES + f);
        acc1 += w1 * __ldg(sup + (size_t)s1 * CLASSES + f);
        acc2 += w2 * __ldg(sup + (size_t)s2 * CLASSES + f);
        acc3 += w3 * __ldg(sup + (size_t)s3 * CLASSES + f);
    }
    for (; e < end; e++)
        acc0 += __ldg(wv + e) * __ldg(sup + (size_t)__ldg(col + e) * CLASSES + f);
    out[(size_t)row * CLASSES + f] = acc0 + acc1 + acc2 + acc3;
}

// ---------------------------------------------------------------------------
// In-place log_softmax over 64 classes (+ bias b2). One warp per row.
// ---------------------------------------------------------------------------
__global__ __launch_bounds__(256)
void logsoftmax_kernel(float* __restrict__ out, const float* __restrict__ b2, int M) {
    int row = blockIdx.x * (blockDim.x / 32) + (threadIdx.x >> 5);
    int lane = threadIdx.x & 31;
    if (row >= M) return;
    float* p = out + (size_t)row * CLASSES;

    float v0 = p[lane]      + __ldg(b2 + lane);
    float v1 = p[lane + 32] + __ldg(b2 + lane + 32);

    float m = fmaxf(v0, v1);
#pragma unroll
    for (int o = 16; o; o >>= 1) m = fmaxf(m, __shfl_xor_sync(0xFFFFFFFFu, m, o));

    float s = expf(v0 - m) + expf(v1 - m);
#pragma unroll
    for (int o = 16; o; o >>= 1) s += __shfl_xor_sync(0xFFFFFFFFu, s, o);

    float lse = m + logf(s);
    p[lane]      = v0 - lse;
    p[lane + 32] = v1 - lse;
}

// ---------------------------------------------------------------------------
// kernel_launch
// ---------------------------------------------------------------------------
extern "C" void kernel_launch(void* const* d_in, const int* in_sizes, int n_in,
                              void* d_out, int out_size) {
    const float* x    = (const float*)d_in[0];
    const float* w1   = (const float*)d_in[1];
    const float* b1   = (const float*)d_in[2];
    const float* w2   = (const float*)d_in[3];
    const float* b2   = (const float*)d_in[4];
    const float* ew   = (const float*)d_in[5];
    const int*   esrc = (const int*)d_in[6];
    const int*   edst = (const int*)d_in[7];
    float*       out  = (float*)d_out;

    float *sup1, *agg1, *sup2, *wv;
    int *deg, *rowptr, *cursor, *col;
    cudaGetSymbolAddress((void**)&sup1, g_sup1);
    cudaGetSymbolAddress((void**)&agg1, g_agg1);
    cudaGetSymbolAddress((void**)&sup2, g_sup2);
    cudaGetSymbolAddress((void**)&deg, g_deg);
    cudaGetSymbolAddress((void**)&rowptr, g_rowptr);
    cudaGetSymbolAddress((void**)&cursor, g_cursor);
    cudaGetSymbolAddress((void**)&col, g_col);
    cudaGetSymbolAddress((void**)&wv, g_wv);

    // --- CSR build (reused by both SpMM layers) ---
    zero_int_kernel<<<(N_NODES + 255) / 256, 256>>>(deg, N_NODES);
    hist_kernel<<<(N_EDGES + 255) / 256, 256>>>(edst, deg);
    scan_kernel<<<1, 1024>>>(deg, rowptr, cursor);
    fill_kernel<<<(N_EDGES + 255) / 256, 256>>>(esrc, edst, ew, cursor, col, wv);

    // --- Layer 1 ---
    {   // sup1 = X @ W1  (tf32 tensor cores)
        dim3 grid(HIDDEN / 128, (N_NODES + 127) / 128);
        gemm_tf32_kernel<<<grid, 256>>>(x, w1, sup1, N_NODES);
    }
    // agg1 = A @ sup1  (gather, no atomics)
    spmm_gather256<<<N_NODES, 256>>>(sup1, rowptr, col, wv, agg1);

    // --- Layer 2 ---
    {   // sup2 = relu(agg1 + b1) @ W2
        dim3 grid(CLASSES / 64, (N_NODES + 127) / 128);
        sgemm_fused_kernel<128, 64, 8, 8, 4><<<grid, 256>>>(
            agg1, w2, b1, sup2, N_NODES, CLASSES, HIDDEN);
    }
    // out = A @ sup2
    spmm_gather64<<<(N_NODES + 3) / 4, 256>>>(sup2, rowptr, col, wv, out);

    // out = log_softmax(out + b2)
    logsoftmax_kernel<<<(N_NODES + 7) / 8, 256>>>(out, b2, N_NODES);
}